// round 1
// baseline (speedup 1.0000x reference)
#include <cuda_runtime.h>
#include <cuda_bf16.h>
#include <cstdint>

#define N_NODES   50000
#define N_EDGES   800000
#define N_FEAT    128
#define HIDDEN    64
#define N_GRAPHS  256

// ---------------- scratch (device globals; no allocation in kernel_launch) ----
__device__ int    d_src[N_EDGES];
__device__ int    d_dst[N_EDGES];
__device__ int    d_batch[N_NODES];
__device__ int    d_flag;                 // 1 => inputs are int64, 0 => int32
__device__ float  d_deg[N_NODES];
__device__ float  d_dis[N_NODES];
__device__ float4 d_g4[N_NODES * 16];     // g = dis * (h @ W)   [50000 x 64]
__device__ float4 d_agg4[N_NODES * 16];   // scatter accumulator [50000 x 64]
__device__ float4 d_h4[N_NODES * 16];     // layer activations   [50000 x 64]
__device__ float  d_pool[N_GRAPHS * HIDDEN];
__device__ float  d_cnt[N_GRAPHS];

// ---------------- dtype detection --------------------------------------------
// If edge_index is int64 (values < 50000, non-negative), every odd 32-bit word
// of the buffer is zero. If int32, odd words are random node ids. Reading the
// first 2048 words (8KB) is in-bounds for both interpretations.
__global__ void k_detect(const int* __restrict__ ebuf) {
    __shared__ int ok;
    if (threadIdx.x == 0) ok = 1;
    __syncthreads();
    int bad = 0;
    for (int t = threadIdx.x; t < 1024; t += blockDim.x)
        if (ebuf[2 * t + 1] != 0) bad = 1;
    if (bad) ok = 0;          // benign race, any writer wins
    __syncthreads();
    if (threadIdx.x == 0) d_flag = ok;
}

__global__ void k_convert(const void* __restrict__ e, const void* __restrict__ b) {
    int i = blockIdx.x * blockDim.x + threadIdx.x;
    int f = d_flag;
    if (i < N_EDGES) {
        if (f) {
            const long long* p = (const long long*)e;
            d_src[i] = (int)p[i];
            d_dst[i] = (int)p[i + N_EDGES];
        } else {
            const int* p = (const int*)e;
            d_src[i] = p[i];
            d_dst[i] = p[i + N_EDGES];
        }
    }
    if (i < N_NODES) {
        d_batch[i] = f ? (int)((const long long*)b)[i] : ((const int*)b)[i];
    }
}

// ---------------- degree / normalization -------------------------------------
__global__ void k_deg_init() {
    int i = blockIdx.x * blockDim.x + threadIdx.x;
    if (i < N_NODES) d_deg[i] = 1.0f;     // self-loop
}
__global__ void k_deg_accum() {
    int i = blockIdx.x * blockDim.x + threadIdx.x;
    if (i < N_EDGES) atomicAdd(&d_deg[d_dst[i]], 1.0f);   // no-return -> RED
}
__global__ void k_dis() {
    int i = blockIdx.x * blockDim.x + threadIdx.x;
    if (i < N_NODES) d_dis[i] = rsqrtf(d_deg[i]);         // deg >= 1 always
}

// ---------------- GEMM layer 1: g = dis * (x @ W1)   [50000x128 @ 128x64] ----
__global__ void __launch_bounds__(256) k_gemm1(const float* __restrict__ x,
                                               const float* __restrict__ W) {
    __shared__ float2 sw[N_FEAT * 32];    // 32 KB
    __shared__ float  sx[8][N_FEAT];      // 4 KB
    int w = threadIdx.x >> 5, l = threadIdx.x & 31;
    const float2* W2 = (const float2*)W;
    for (int i = threadIdx.x; i < N_FEAT * 32; i += 256) sw[i] = W2[i];
    int row0 = blockIdx.x * 8;
    for (int i = threadIdx.x; i < 8 * N_FEAT; i += 256) {
        int r = i >> 7, c = i & 127;
        sx[r][c] = x[(row0 + r) * N_FEAT + c];
    }
    __syncthreads();
    float2 acc = make_float2(0.f, 0.f);
#pragma unroll 16
    for (int k = 0; k < N_FEAT; k++) {
        float  xv = sx[w][k];
        float2 wv = sw[k * 32 + l];
        acc.x += xv * wv.x;
        acc.y += xv * wv.y;
    }
    int row = row0 + w;
    float s = d_dis[row];
    ((float2*)d_g4)[row * 32 + l] = make_float2(acc.x * s, acc.y * s);
}

// ---------------- GEMM layer 2: g = dis * (h @ W2)   [50000x64 @ 64x64] ------
__global__ void __launch_bounds__(256) k_gemm2(const float* __restrict__ W) {
    __shared__ float2 sw[HIDDEN * 32];    // 16 KB
    __shared__ float  sx[8][HIDDEN];      // 2 KB
    int w = threadIdx.x >> 5, l = threadIdx.x & 31;
    const float2* W2 = (const float2*)W;
    for (int i = threadIdx.x; i < HIDDEN * 32; i += 256) sw[i] = W2[i];
    int row0 = blockIdx.x * 8;
    const float* h = (const float*)d_h4;
    for (int i = threadIdx.x; i < 8 * HIDDEN; i += 256) {
        int r = i >> 6, c = i & 63;
        sx[r][c] = h[(row0 + r) * HIDDEN + c];
    }
    __syncthreads();
    float2 acc = make_float2(0.f, 0.f);
#pragma unroll 16
    for (int k = 0; k < HIDDEN; k++) {
        float  xv = sx[w][k];
        float2 wv = sw[k * 32 + l];
        acc.x += xv * wv.x;
        acc.y += xv * wv.y;
    }
    int row = row0 + w;
    float s = d_dis[row];
    ((float2*)d_g4)[row * 32 + l] = make_float2(acc.x * s, acc.y * s);
}

// ---------------- zero / scatter / epilogue ----------------------------------
__global__ void k_zero_agg() {
    int i = blockIdx.x * blockDim.x + threadIdx.x;
    if (i < N_NODES * 16) d_agg4[i] = make_float4(0.f, 0.f, 0.f, 0.f);
}

__global__ void __launch_bounds__(256) k_scatter() {
    int idx = blockIdx.x * blockDim.x + threadIdx.x;   // N_EDGES*16 = 12.8M
    int e = idx >> 4, c = idx & 15;
    int s = d_src[e], d = d_dst[e];
    float4 v = d_g4[s * 16 + c];
    float* p = (float*)&d_agg4[d * 16 + c];
    asm volatile("red.global.add.v4.f32 [%0], {%1, %2, %3, %4};"
                 :: "l"(p), "f"(v.x), "f"(v.y), "f"(v.z), "f"(v.w)
                 : "memory");
}

// h = relu(dis * (agg + g) + bias)   (agg + g folds in the self-loop term)
__global__ void k_finish(const float* __restrict__ bias) {
    int i = blockIdx.x * blockDim.x + threadIdx.x;     // N_NODES*16
    int node = i >> 4, c = i & 15;
    float s = d_dis[node];
    float4 a = d_agg4[i], g = d_g4[i];
    float4 bb = ((const float4*)bias)[c];
    float4 r;
    r.x = fmaxf(s * (a.x + g.x) + bb.x, 0.f);
    r.y = fmaxf(s * (a.y + g.y) + bb.y, 0.f);
    r.z = fmaxf(s * (a.z + g.z) + bb.z, 0.f);
    r.w = fmaxf(s * (a.w + g.w) + bb.w, 0.f);
    d_h4[i] = r;
}

// ---------------- pooling + MLP head -----------------------------------------
__global__ void k_zero_pool() {
    int i = blockIdx.x * blockDim.x + threadIdx.x;
    if (i < N_GRAPHS * HIDDEN) d_pool[i] = 0.f;
    if (i < N_GRAPHS) d_cnt[i] = 0.f;
}

__global__ void k_pool() {
    int i = blockIdx.x * blockDim.x + threadIdx.x;     // N_NODES*16
    int node = i >> 4, c = i & 15;
    int b = d_batch[node];
    float4 v = d_h4[i];
    float* p = &d_pool[b * HIDDEN + c * 4];
    asm volatile("red.global.add.v4.f32 [%0], {%1, %2, %3, %4};"
                 :: "l"(p), "f"(v.x), "f"(v.y), "f"(v.z), "f"(v.w)
                 : "memory");
    if (c == 0) atomicAdd(&d_cnt[b], 1.0f);
}

__global__ void k_mlp(const float* __restrict__ Wm1, const float* __restrict__ bm1,
                      const float* __restrict__ Wm2, const float* __restrict__ bm2,
                      float* __restrict__ out) {
    __shared__ float sp[HIDDEN];
    __shared__ float sred[HIDDEN];
    int g = blockIdx.x, j = threadIdx.x;
    float inv = 1.0f / fmaxf(d_cnt[g], 1.0f);
    sp[j] = d_pool[g * HIDDEN + j] * inv;
    __syncthreads();
    float acc = bm1[j];
#pragma unroll
    for (int k = 0; k < HIDDEN; k++) acc += sp[k] * Wm1[k * HIDDEN + j];
    float v = fmaxf(acc, 0.f) * Wm2[j];
    sred[j] = v;
    __syncthreads();
    if (j < 32) {
        float t = sred[j] + sred[j + 32];
        for (int o = 16; o; o >>= 1) t += __shfl_down_sync(0xffffffff, t, o);
        if (j == 0) out[g] = t + bm2[0];
    }
}

// ---------------- launch ------------------------------------------------------
extern "C" void kernel_launch(void* const* d_in, const int* in_sizes, int n_in,
                              void* d_out, int out_size) {
    const float* x   = (const float*)d_in[0];
    const void*  ei  = d_in[1];
    const void*  bt  = d_in[2];
    const float* W1  = (const float*)d_in[3];
    const float* b1  = (const float*)d_in[4];
    const float* W2  = (const float*)d_in[5];
    const float* b2  = (const float*)d_in[6];
    const float* Wm1 = (const float*)d_in[7];
    const float* bm1 = (const float*)d_in[8];
    const float* Wm2 = (const float*)d_in[9];
    const float* bm2 = (const float*)d_in[10];
    float* out = (float*)d_out;

    k_detect<<<1, 256>>>((const int*)ei);
    k_convert<<<(N_EDGES + 255) / 256, 256>>>(ei, bt);

    k_deg_init<<<(N_NODES + 255) / 256, 256>>>();
    k_deg_accum<<<(N_EDGES + 255) / 256, 256>>>();
    k_dis<<<(N_NODES + 255) / 256, 256>>>();

    // layer 1
    k_gemm1<<<N_NODES / 8, 256>>>(x, W1);
    k_zero_agg<<<(N_NODES * 16 + 255) / 256, 256>>>();
    k_scatter<<<(N_EDGES * 16) / 256, 256>>>();
    k_finish<<<(N_NODES * 16) / 256, 256>>>(b1);

    // layer 2
    k_gemm2<<<N_NODES / 8, 256>>>(W2);
    k_zero_agg<<<(N_NODES * 16 + 255) / 256, 256>>>();
    k_scatter<<<(N_EDGES * 16) / 256, 256>>>();
    k_finish<<<(N_NODES * 16) / 256, 256>>>(b2);

    // pool + head
    k_zero_pool<<<(N_GRAPHS * HIDDEN + 255) / 256, 256>>>();
    k_pool<<<(N_NODES * 16) / 256, 256>>>();
    k_mlp<<<N_GRAPHS, HIDDEN>>>(Wm1, bm1, Wm2, bm2, out);
}

// round 2
// speedup vs baseline: 1.1118x; 1.1118x over previous
#include <cuda_runtime.h>
#include <cuda_bf16.h>
#include <cstdint>

#define N_NODES   50000
#define N_EDGES   800000
#define N_FEAT    128
#define HIDDEN    64
#define N_GRAPHS  256

// ---------------- scratch ----------------------------------------------------
__device__ int    d_src[N_EDGES];
__device__ int    d_dst[N_EDGES];
__device__ int    d_csr_src[N_EDGES];
__device__ int    d_batch[N_NODES];
__device__ int    d_flag;                 // 1 => int64 inputs, 0 => int32
__device__ int    d_ecnt[N_NODES];        // edge count per dst (histogram)
__device__ int    d_ptr[N_NODES];         // CSR row start
__device__ int    d_cur[N_NODES];         // fill cursor
__device__ float  d_dis[N_NODES];         // deg^-1/2 (deg = ecnt+1 self loop)
__device__ float4 d_g4[N_NODES * 16];     // g = dis * (h @ W)   [50000 x 64]
__device__ float2 d_h2[N_NODES * 32];     // activations         [50000 x 64]
__device__ float  d_pool[N_GRAPHS * HIDDEN];
__device__ float  d_cnt[N_GRAPHS];

// ---------------- detect dtype + zero scratch ---------------------------------
// int64 edge_index with values < 50000 => every odd 32-bit word is zero.
__global__ void k_detect(const int* __restrict__ ebuf) {
    int i = blockIdx.x * blockDim.x + threadIdx.x;
    if (i < N_NODES) d_ecnt[i] = 0;
    if (i < N_GRAPHS * HIDDEN) d_pool[i] = 0.f;
    if (i < N_GRAPHS) d_cnt[i] = 0.f;
    if (blockIdx.x == 0) {
        __shared__ int ok;
        if (threadIdx.x == 0) ok = 1;
        __syncthreads();
        int bad = 0;
        for (int t = threadIdx.x; t < 1024; t += blockDim.x)
            if (ebuf[2 * t + 1] != 0) bad = 1;
        if (bad) ok = 0;
        __syncthreads();
        if (threadIdx.x == 0) d_flag = ok;
    }
}

// ---------------- convert indices + histogram + batch -------------------------
__global__ void k_convert(const void* __restrict__ e, const void* __restrict__ b) {
    int i = blockIdx.x * blockDim.x + threadIdx.x;
    int f = d_flag;
    if (i < N_EDGES) {
        int s, d;
        if (f) {
            const long long* p = (const long long*)e;
            s = (int)p[i]; d = (int)p[i + N_EDGES];
        } else {
            const int* p = (const int*)e;
            s = p[i]; d = p[i + N_EDGES];
        }
        d_src[i] = s; d_dst[i] = d;
        atomicAdd(&d_ecnt[d], 1);
    }
    if (i < N_NODES) {
        int bb = f ? (int)((const long long*)b)[i] : ((const int*)b)[i];
        d_batch[i] = bb;
        atomicAdd(&d_cnt[bb], 1.0f);
    }
}

// ---------------- single-block exclusive scan + dis ----------------------------
__global__ void __launch_bounds__(1024) k_scan() {
    __shared__ int part[1024];
    const int CH = 49;                       // 49*1024 = 50176 >= 50000
    int t = threadIdx.x;
    int base = t * CH;
    int sum = 0;
    for (int j = 0; j < CH; j++) {
        int i = base + j;
        if (i < N_NODES) sum += d_ecnt[i];
    }
    part[t] = sum;
    __syncthreads();
    for (int off = 1; off < 1024; off <<= 1) {
        int v = (t >= off) ? part[t - off] : 0;
        __syncthreads();
        part[t] += v;
        __syncthreads();
    }
    int run = part[t] - sum;                 // exclusive prefix
    for (int j = 0; j < CH; j++) {
        int i = base + j;
        if (i < N_NODES) {
            int c = d_ecnt[i];
            d_ptr[i] = run;
            d_cur[i] = run;
            d_dis[i] = rsqrtf((float)(c + 1));
            run += c;
        }
    }
}

// ---------------- CSR fill -----------------------------------------------------
__global__ void k_fill() {
    int i = blockIdx.x * blockDim.x + threadIdx.x;
    if (i < N_EDGES) {
        int s = d_src[i], d = d_dst[i];
        int pos = atomicAdd(&d_cur[d], 1);
        d_csr_src[pos] = s;
    }
}

// ---------------- GEMM: G = dis * (X @ W),  X:[N,K], W:[K,64] ------------------
// block = 256 thr = 8 warps; block handles 64 rows; warp 8 rows;
// lane = h*16+l16: half h -> 4 rows, l16 -> 4 cols (float4).
template<int K>
__global__ void __launch_bounds__(256) k_gemm(const float* __restrict__ X,
                                              const float* __restrict__ W,
                                              float4* __restrict__ G) {
    __shared__ float4 sw[K * 16];
    __shared__ float  sx[64][K];
    int tid = threadIdx.x;
    int w = tid >> 5, lane = tid & 31, h = lane >> 4, l16 = lane & 15;
    for (int i = tid; i < K * 16; i += 256) sw[i] = ((const float4*)W)[i];
    int row0 = blockIdx.x * 64;
    const float4* X4 = (const float4*)X;
    for (int i = tid; i < 64 * (K / 4); i += 256) {
        int r = i / (K / 4), c = i % (K / 4);
        int row = row0 + r;
        float4 v = (row < N_NODES) ? X4[row * (K / 4) + c] : make_float4(0.f,0.f,0.f,0.f);
        ((float4*)&sx[r][0])[c] = v;
    }
    __syncthreads();
    int rbase = w * 8 + h * 4;
    float4 a0 = {0,0,0,0}, a1 = {0,0,0,0}, a2 = {0,0,0,0}, a3 = {0,0,0,0};
#pragma unroll 8
    for (int k = 0; k < K; k++) {
        float4 wv = sw[k * 16 + l16];
        float x0 = sx[rbase + 0][k];
        float x1 = sx[rbase + 1][k];
        float x2 = sx[rbase + 2][k];
        float x3 = sx[rbase + 3][k];
        a0.x += x0*wv.x; a0.y += x0*wv.y; a0.z += x0*wv.z; a0.w += x0*wv.w;
        a1.x += x1*wv.x; a1.y += x1*wv.y; a1.z += x1*wv.z; a1.w += x1*wv.w;
        a2.x += x2*wv.x; a2.y += x2*wv.y; a2.z += x2*wv.z; a2.w += x2*wv.w;
        a3.x += x3*wv.x; a3.y += x3*wv.y; a3.z += x3*wv.z; a3.w += x3*wv.w;
    }
    float4 acc[4] = {a0, a1, a2, a3};
#pragma unroll
    for (int i = 0; i < 4; i++) {
        int row = row0 + rbase + i;
        if (row < N_NODES) {
            float s = d_dis[row];
            float4 v = acc[i];
            G[row * 16 + l16] = make_float4(v.x*s, v.y*s, v.z*s, v.w*s);
        }
    }
}

// ---------------- CSR gather aggregate (1 warp / node) -------------------------
__device__ __forceinline__ float2 agg_node(int node, int lane) {
    const float2* g2 = (const float2*)d_g4;
    int start = d_ptr[node];
    int n = d_ecnt[node];
    float2 acc = g2[node * 32 + lane];      // self-loop term
    int j = 0;
    for (; j + 4 <= n; j += 4) {
        int s0 = d_csr_src[start + j + 0];
        int s1 = d_csr_src[start + j + 1];
        int s2 = d_csr_src[start + j + 2];
        int s3 = d_csr_src[start + j + 3];
        float2 a = g2[s0 * 32 + lane];
        float2 b = g2[s1 * 32 + lane];
        float2 c = g2[s2 * 32 + lane];
        float2 d = g2[s3 * 32 + lane];
        acc.x += (a.x + b.x) + (c.x + d.x);
        acc.y += (a.y + b.y) + (c.y + d.y);
    }
    for (; j < n; j++) {
        int s = d_csr_src[start + j];
        float2 a = g2[s * 32 + lane];
        acc.x += a.x; acc.y += a.y;
    }
    return acc;
}

__global__ void __launch_bounds__(256) k_agg1(const float* __restrict__ bias) {
    int node = blockIdx.x * 8 + (threadIdx.x >> 5);
    int lane = threadIdx.x & 31;
    float2 acc = agg_node(node, lane);
    float s = d_dis[node];
    float2 bb = ((const float2*)bias)[lane];
    float2 r;
    r.x = fmaxf(s * acc.x + bb.x, 0.f);
    r.y = fmaxf(s * acc.y + bb.y, 0.f);
    d_h2[node * 32 + lane] = r;
}

__global__ void __launch_bounds__(256) k_agg2(const float* __restrict__ bias) {
    int node = blockIdx.x * 8 + (threadIdx.x >> 5);
    int lane = threadIdx.x & 31;
    float2 acc = agg_node(node, lane);
    float s = d_dis[node];
    float2 bb = ((const float2*)bias)[lane];
    float rx = fmaxf(s * acc.x + bb.x, 0.f);
    float ry = fmaxf(s * acc.y + bb.y, 0.f);
    int b = d_batch[node];
    float* p = &d_pool[b * HIDDEN + lane * 2];
    asm volatile("red.global.add.v2.f32 [%0], {%1, %2};"
                 :: "l"(p), "f"(rx), "f"(ry) : "memory");
}

// ---------------- MLP head -----------------------------------------------------
__global__ void k_mlp(const float* __restrict__ Wm1, const float* __restrict__ bm1,
                      const float* __restrict__ Wm2, const float* __restrict__ bm2,
                      float* __restrict__ out) {
    __shared__ float sp[HIDDEN];
    __shared__ float sred[HIDDEN];
    int g = blockIdx.x, j = threadIdx.x;
    float inv = 1.0f / fmaxf(d_cnt[g], 1.0f);
    sp[j] = d_pool[g * HIDDEN + j] * inv;
    __syncthreads();
    float acc = bm1[j];
#pragma unroll
    for (int k = 0; k < HIDDEN; k++) acc += sp[k] * Wm1[k * HIDDEN + j];
    float v = fmaxf(acc, 0.f) * Wm2[j];
    sred[j] = v;
    __syncthreads();
    if (j < 32) {
        float t = sred[j] + sred[j + 32];
        for (int o = 16; o; o >>= 1) t += __shfl_down_sync(0xffffffff, t, o);
        if (j == 0) out[g] = t + bm2[0];
    }
}

// ---------------- launch -------------------------------------------------------
extern "C" void kernel_launch(void* const* d_in, const int* in_sizes, int n_in,
                              void* d_out, int out_size) {
    const float* x   = (const float*)d_in[0];
    const void*  ei  = d_in[1];
    const void*  bt  = d_in[2];
    const float* W1  = (const float*)d_in[3];
    const float* b1  = (const float*)d_in[4];
    const float* W2  = (const float*)d_in[5];
    const float* b2  = (const float*)d_in[6];
    const float* Wm1 = (const float*)d_in[7];
    const float* bm1 = (const float*)d_in[8];
    const float* Wm2 = (const float*)d_in[9];
    const float* bm2 = (const float*)d_in[10];
    float* out = (float*)d_out;

    float4* g4;  cudaGetSymbolAddress((void**)&g4, d_g4);
    float2* h2;  cudaGetSymbolAddress((void**)&h2, d_h2);

    k_detect<<<200, 256>>>((const int*)ei);
    k_convert<<<(N_EDGES + 255) / 256, 256>>>(ei, bt);
    k_scan<<<1, 1024>>>();
    k_fill<<<(N_EDGES + 255) / 256, 256>>>();

    k_gemm<N_FEAT><<<(N_NODES + 63) / 64, 256>>>(x, W1, g4);
    k_agg1<<<N_NODES / 8, 256>>>(b1);

    k_gemm<HIDDEN><<<(N_NODES + 63) / 64, 256>>>((const float*)h2, W2, g4);
    k_agg2<<<N_NODES / 8, 256>>>(b2);

    k_mlp<<<N_GRAPHS, HIDDEN>>>(Wm1, bm1, Wm2, bm2, out);
}

// round 3
// speedup vs baseline: 1.6754x; 1.5070x over previous
#include <cuda_runtime.h>
#include <cuda_bf16.h>
#include <cstdint>

#define N_NODES   50000
#define N_EDGES   800000
#define N_FEAT    128
#define HIDDEN    64
#define N_GRAPHS  256
#define NB_SCAN   196               // 196*256 = 50176 >= N_NODES

// ---------------- scratch ----------------------------------------------------
__device__ __align__(16) int    d_src[N_EDGES];
__device__ __align__(16) int    d_dst[N_EDGES];
__device__ __align__(16) int    d_csr_src[N_EDGES];
__device__ int    d_batch[N_NODES];
__device__ int    d_flag;                 // 1 => int64 inputs, 0 => int32
__device__ int    d_ecnt[N_NODES];        // edges per dst
__device__ int    d_ptr[N_NODES];         // CSR row start
__device__ int    d_cur[N_NODES];         // fill cursor
__device__ int    d_bsum[256];            // per-block scan sums
__device__ int    d_boff[256];            // per-block scan offsets
__device__ float  d_dis[N_NODES];
__device__ __align__(16) float2 d_ga[(N_NODES + 1) * 32];  // layer-1 g (+zero row)
__device__ __align__(16) float2 d_gb[(N_NODES + 1) * 32];  // layer-2 g (+zero row)
__device__ float  d_pool[N_GRAPHS * HIDDEN];
__device__ float  d_cnt[N_GRAPHS];

// ---------------- detect dtype + zero scratch ---------------------------------
__global__ void k_detect(const int* __restrict__ ebuf) {
    int i = blockIdx.x * blockDim.x + threadIdx.x;
    if (i < N_NODES) d_ecnt[i] = 0;
    if (i < N_GRAPHS * HIDDEN) d_pool[i] = 0.f;
    if (i < N_GRAPHS) d_cnt[i] = 0.f;
    if (i < 32) {                            // zero rows for padded gathers
        d_ga[N_NODES * 32 + i] = make_float2(0.f, 0.f);
        d_gb[N_NODES * 32 + i] = make_float2(0.f, 0.f);
    }
    if (blockIdx.x == 0) {
        __shared__ int ok;
        if (threadIdx.x == 0) ok = 1;
        __syncthreads();
        int bad = 0;
        for (int t = threadIdx.x; t < 1024; t += blockDim.x)
            if (ebuf[2 * t + 1] != 0) bad = 1;
        if (bad) ok = 0;
        __syncthreads();
        if (threadIdx.x == 0) d_flag = ok;
    }
}

// ---------------- convert indices (4 edges/thread) + histogram + batch --------
__global__ void k_convert(const void* __restrict__ e, const void* __restrict__ b) {
    int t = blockIdx.x * blockDim.x + threadIdx.x;
    int f = d_flag;
    int e0 = t * 4;
    if (e0 < N_EDGES) {                      // N_EDGES % 4 == 0 -> full quads
        int s[4], dd[4];
        if (f) {
            const long long* p = (const long long*)e;
#pragma unroll
            for (int k = 0; k < 4; k++) { s[k] = (int)p[e0 + k]; dd[k] = (int)p[e0 + k + N_EDGES]; }
        } else {
            const int* p = (const int*)e;
#pragma unroll
            for (int k = 0; k < 4; k++) { s[k] = p[e0 + k]; dd[k] = p[e0 + k + N_EDGES]; }
        }
        ((int4*)d_src)[t] = make_int4(s[0], s[1], s[2], s[3]);
        ((int4*)d_dst)[t] = make_int4(dd[0], dd[1], dd[2], dd[3]);
#pragma unroll
        for (int k = 0; k < 4; k++) atomicAdd(&d_ecnt[dd[k]], 1);
    }
    if (t < N_NODES) {
        int bb = f ? (int)((const long long*)b)[t] : ((const int*)b)[t];
        d_batch[t] = bb;
        atomicAdd(&d_cnt[bb], 1.0f);
    }
}

// ---------------- coalesced 3-stage scan ---------------------------------------
__global__ void k_scan1() {
    __shared__ int sm[256];
    int t = threadIdx.x, i = blockIdx.x * 256 + t;
    sm[t] = (i < N_NODES) ? d_ecnt[i] : 0;
    __syncthreads();
    for (int s = 128; s; s >>= 1) { if (t < s) sm[t] += sm[t + s]; __syncthreads(); }
    if (t == 0) d_bsum[blockIdx.x] = sm[0];
}
__global__ void k_scan2() {
    __shared__ int sm[256];
    int t = threadIdx.x;
    int v = (t < NB_SCAN) ? d_bsum[t] : 0;
    sm[t] = v;
    __syncthreads();
    for (int off = 1; off < 256; off <<= 1) {
        int u = (t >= off) ? sm[t - off] : 0;
        __syncthreads();
        sm[t] += u;
        __syncthreads();
    }
    d_boff[t] = sm[t] - v;                   // exclusive
}
__global__ void k_scan3() {
    __shared__ int sm[256];
    int t = threadIdx.x, i = blockIdx.x * 256 + t;
    int v = (i < N_NODES) ? d_ecnt[i] : 0;
    sm[t] = v;
    __syncthreads();
    for (int off = 1; off < 256; off <<= 1) {
        int u = (t >= off) ? sm[t - off] : 0;
        __syncthreads();
        sm[t] += u;
        __syncthreads();
    }
    if (i < N_NODES) {
        int p = d_boff[blockIdx.x] + sm[t] - v;
        d_ptr[i] = p;
        d_cur[i] = p;
        d_dis[i] = rsqrtf((float)(v + 1));
    }
}

// ---------------- CSR fill (4 edges/thread, batched atomics) -------------------
__global__ void k_fill() {
    int t = blockIdx.x * blockDim.x + threadIdx.x;
    int e0 = t * 4;
    if (e0 >= N_EDGES) return;
    int4 s4 = ((const int4*)d_src)[t];
    int4 d4 = ((const int4*)d_dst)[t];
    int p0 = atomicAdd(&d_cur[d4.x], 1);
    int p1 = atomicAdd(&d_cur[d4.y], 1);
    int p2 = atomicAdd(&d_cur[d4.z], 1);
    int p3 = atomicAdd(&d_cur[d4.w], 1);
    d_csr_src[p0] = s4.x;
    d_csr_src[p1] = s4.y;
    d_csr_src[p2] = s4.z;
    d_csr_src[p3] = s4.w;
}

// ---------------- GEMM1: Ga = dis * (X @ W1)  [50000x128 @ 128x64] -------------
__global__ void __launch_bounds__(256) k_gemm1(const float* __restrict__ X,
                                               const float* __restrict__ W) {
    __shared__ float4 sw[N_FEAT * 16];       // 32 KB
    __shared__ float  sx[64][N_FEAT];        // 32 KB
    int tid = threadIdx.x;
    int w = tid >> 5, lane = tid & 31, h = lane >> 4, l16 = lane & 15;
    for (int i = tid; i < N_FEAT * 16; i += 256) sw[i] = ((const float4*)W)[i];
    int row0 = blockIdx.x * 64;
    const float4* X4 = (const float4*)X;
    for (int i = tid; i < 64 * 32; i += 256) {
        int r = i >> 5, c = i & 31;
        int row = row0 + r;
        float4 v = (row < N_NODES) ? X4[row * 32 + c] : make_float4(0.f, 0.f, 0.f, 0.f);
        ((float4*)&sx[r][0])[c] = v;
    }
    __syncthreads();
    int rbase = w * 8 + h * 4;
    float4 a0 = {0,0,0,0}, a1 = {0,0,0,0}, a2 = {0,0,0,0}, a3 = {0,0,0,0};
#pragma unroll 8
    for (int k = 0; k < N_FEAT; k++) {
        float4 wv = sw[k * 16 + l16];
        float x0 = sx[rbase + 0][k];
        float x1 = sx[rbase + 1][k];
        float x2 = sx[rbase + 2][k];
        float x3 = sx[rbase + 3][k];
        a0.x += x0*wv.x; a0.y += x0*wv.y; a0.z += x0*wv.z; a0.w += x0*wv.w;
        a1.x += x1*wv.x; a1.y += x1*wv.y; a1.z += x1*wv.z; a1.w += x1*wv.w;
        a2.x += x2*wv.x; a2.y += x2*wv.y; a2.z += x2*wv.z; a2.w += x2*wv.w;
        a3.x += x3*wv.x; a3.y += x3*wv.y; a3.z += x3*wv.z; a3.w += x3*wv.w;
    }
    float4 acc[4] = {a0, a1, a2, a3};
#pragma unroll
    for (int i = 0; i < 4; i++) {
        int row = row0 + rbase + i;
        if (row < N_NODES) {
            float s = d_dis[row];
            float4 v = acc[i];
            ((float4*)d_ga)[row * 16 + l16] = make_float4(v.x*s, v.y*s, v.z*s, v.w*s);
        }
    }
}

// ---------------- CSR gather (1 warp/node, shfl indices, unroll 8) -------------
__device__ __forceinline__ float2 agg_node(const float2* __restrict__ g2,
                                           int node, int lane) {
    int start = d_ptr[node];
    int n = d_ecnt[node];
    float2 accA = g2[node * 32 + lane];      // self-loop term
    float2 accB = make_float2(0.f, 0.f);
    for (int base = 0; base < n; base += 32) {
        int rem = n - base;
        int idx = (lane < rem) ? d_csr_src[start + base + lane] : N_NODES;  // zero row
        int mm = rem < 32 ? rem : 32;
        for (int jj = 0; jj < mm; jj += 8) {
#pragma unroll
            for (int j = 0; j < 8; j++) {
                int s = __shfl_sync(0xffffffffu, idx, jj + j);
                float2 a = g2[s * 32 + lane];
                if (j & 1) { accB.x += a.x; accB.y += a.y; }
                else       { accA.x += a.x; accA.y += a.y; }
            }
        }
    }
    return make_float2(accA.x + accB.x, accA.y + accB.y);
}

// ---------------- agg1 + fused GEMM2: Gb = dis * (relu(dis*agg+b1) @ W2) -------
__global__ void __launch_bounds__(256) k_agg1(const float* __restrict__ bias,
                                              const float* __restrict__ W2) {
    __shared__ float2 sw2[HIDDEN * 32];      // 16 KB
    __shared__ float  sh[8][HIDDEN];         // 2 KB
    int tid = threadIdx.x;
    for (int i = tid; i < HIDDEN * 32; i += 256) sw2[i] = ((const float2*)W2)[i];
    __syncthreads();
    int w = tid >> 5, lane = tid & 31;
    int node = blockIdx.x * 8 + w;
    float2 acc = agg_node(d_ga, node, lane);
    float s = d_dis[node];
    float2 bb = ((const float2*)bias)[lane];
    sh[w][2 * lane]     = fmaxf(s * acc.x + bb.x, 0.f);
    sh[w][2 * lane + 1] = fmaxf(s * acc.y + bb.y, 0.f);
    __syncwarp();
    float2 o = make_float2(0.f, 0.f);
#pragma unroll
    for (int k = 0; k < HIDDEN; k++) {
        float hk = sh[w][k];
        float2 wv = sw2[k * 32 + lane];
        o.x += hk * wv.x;
        o.y += hk * wv.y;
    }
    d_gb[node * 32 + lane] = make_float2(o.x * s, o.y * s);
}

// ---------------- agg2 + pooled RED --------------------------------------------
__global__ void __launch_bounds__(256) k_agg2(const float* __restrict__ bias) {
    int tid = threadIdx.x;
    int w = tid >> 5, lane = tid & 31;
    int node = blockIdx.x * 8 + w;
    float2 acc = agg_node(d_gb, node, lane);
    float s = d_dis[node];
    float2 bb = ((const float2*)bias)[lane];
    float rx = fmaxf(s * acc.x + bb.x, 0.f);
    float ry = fmaxf(s * acc.y + bb.y, 0.f);
    int b = d_batch[node];
    float* p = &d_pool[b * HIDDEN + lane * 2];
    asm volatile("red.global.add.v2.f32 [%0], {%1, %2};"
                 :: "l"(p), "f"(rx), "f"(ry) : "memory");
}

// ---------------- MLP head ------------------------------------------------------
__global__ void k_mlp(const float* __restrict__ Wm1, const float* __restrict__ bm1,
                      const float* __restrict__ Wm2, const float* __restrict__ bm2,
                      float* __restrict__ out) {
    __shared__ float sp[HIDDEN];
    __shared__ float sred[HIDDEN];
    int g = blockIdx.x, j = threadIdx.x;
    float inv = 1.0f / fmaxf(d_cnt[g], 1.0f);
    sp[j] = d_pool[g * HIDDEN + j] * inv;
    __syncthreads();
    float acc = bm1[j];
#pragma unroll
    for (int k = 0; k < HIDDEN; k++) acc += sp[k] * Wm1[k * HIDDEN + j];
    float v = fmaxf(acc, 0.f) * Wm2[j];
    sred[j] = v;
    __syncthreads();
    if (j < 32) {
        float t = sred[j] + sred[j + 32];
        for (int o = 16; o; o >>= 1) t += __shfl_down_sync(0xffffffff, t, o);
        if (j == 0) out[g] = t + bm2[0];
    }
}

// ---------------- launch --------------------------------------------------------
extern "C" void kernel_launch(void* const* d_in, const int* in_sizes, int n_in,
                              void* d_out, int out_size) {
    const float* x   = (const float*)d_in[0];
    const void*  ei  = d_in[1];
    const void*  bt  = d_in[2];
    const float* W1  = (const float*)d_in[3];
    const float* b1  = (const float*)d_in[4];
    const float* W2  = (const float*)d_in[5];
    const float* b2  = (const float*)d_in[6];
    const float* Wm1 = (const float*)d_in[7];
    const float* bm1 = (const float*)d_in[8];
    const float* Wm2 = (const float*)d_in[9];
    const float* bm2 = (const float*)d_in[10];
    float* out = (float*)d_out;

    k_detect<<<200, 256>>>((const int*)ei);
    k_convert<<<(N_EDGES / 4 + 255) / 256, 256>>>(ei, bt);
    k_scan1<<<NB_SCAN, 256>>>();
    k_scan2<<<1, 256>>>();
    k_scan3<<<NB_SCAN, 256>>>();
    k_fill<<<(N_EDGES / 4 + 255) / 256, 256>>>();

    k_gemm1<<<(N_NODES + 63) / 64, 256>>>(x, W1);
    k_agg1<<<N_NODES / 8, 256>>>(b1, W2);
    k_agg2<<<N_NODES / 8, 256>>>(b2);

    k_mlp<<<N_GRAPHS, HIDDEN>>>(Wm1, bm1, Wm2, bm2, out);
}